// round 11
// baseline (speedup 1.0000x reference)
#include <cuda_runtime.h>
#include <cooperative_groups.h>
#include <cstdint>

namespace cg = cooperative_groups;

#define T_STEPS 512
#define BATCH   256
#define IN0     128
#define HID     256
#define G3      768   // 3*HID

// ---------------- scratch (static device arrays; allocation-free) ------------
__device__ float g_gi[(size_t)T_STEPS * BATCH * G3];   // reused by both layers
__device__ float g_h1[(size_t)T_STEPS * BATCH * HID];  // layer-0 outputs
__device__ float g_h2[BATCH * HID];                    // final hidden state

// ======================= helpers ========================
__device__ __forceinline__ float f2tf32(float x) {
    float r;
    asm("cvt.rna.tf32.f32 %0, %1;" : "=f"(r) : "f"(x));
    return r;
}

__device__ __forceinline__ void mma_tf32(float* d, const float* a, const float* b) {
    asm volatile(
        "mma.sync.aligned.m16n8k8.row.col.f32.tf32.tf32.f32 "
        "{%0,%1,%2,%3}, {%4,%5,%6,%7}, {%8,%9}, {%0,%1,%2,%3};"
        : "+f"(d[0]), "+f"(d[1]), "+f"(d[2]), "+f"(d[3])
        : "r"(__float_as_uint(a[0])), "r"(__float_as_uint(a[1])),
          "r"(__float_as_uint(a[2])), "r"(__float_as_uint(a[3])),
          "r"(__float_as_uint(b[0])), "r"(__float_as_uint(b[1])));
}

__device__ __forceinline__ void cp_async16(uint32_t dst, const void* src) {
    asm volatile("cp.async.cg.shared.global [%0], [%1], 16;"
                 :: "r"(dst), "l"(src) : "memory");
}

__device__ __forceinline__ float tanh_fast(float x) {
    float r;
    asm("tanh.approx.f32 %0, %1;" : "=f"(r) : "f"(x));
    return r;
}

#define MBAR_INIT(addr, cnt) \
    asm volatile("mbarrier.init.shared.b64 [%0], %1;" \
                 :: "r"((uint32_t)(addr)), "r"((uint32_t)(cnt)) : "memory")

// arrive (release, cluster scope) on rank rk's mbarrier at the same smem offset
#define MBAR_ARRIVE_RANK(local_addr, rk)                                        \
    asm volatile("{\n\t.reg .b32 ra;\n\t"                                       \
        "mapa.shared::cluster.u32 ra, %0, %1;\n\t"                              \
        "mbarrier.arrive.release.cluster.shared::cluster.b64 _, [ra];\n\t}"     \
        :: "r"((uint32_t)(local_addr)), "r"((uint32_t)(rk)) : "memory")

#define MBAR_WAIT(addr, par) do {                                               \
    uint32_t _m = (uint32_t)(addr); uint32_t _p = (uint32_t)(par); uint32_t _d; \
    asm volatile("{\n\t.reg .pred p;\n\t"                                       \
        "mbarrier.try_wait.parity.acquire.cluster.shared::cta.b64 p, [%1], %2;\n\t" \
        "selp.b32 %0, 1, 0, p;\n\t}"                                            \
        : "=r"(_d) : "r"(_m), "r"(_p) : "memory");                              \
    if (!_d) {                                                                  \
        asm volatile("{\n\t.reg .pred P1;\n\t"                                  \
            "WL_%=:\n\t"                                                        \
            "mbarrier.try_wait.parity.acquire.cluster.shared::cta.b64 P1, [%0], %1, 0x989680;\n\t" \
            "@P1 bra.uni WD_%=;\n\t"                                            \
            "bra.uni WL_%=;\n\t"                                                \
            "WD_%=:\n\t}"                                                       \
            :: "r"(_m), "r"(_p) : "memory");                                    \
    }                                                                           \
} while (0)

// =============================================================================
// HMMA tf32 GEMM:  C[M,N] = A[M,K] @ Bw[N,K]^T + bias[N]   (validated R4)
// =============================================================================
#define PITCH 136

__global__ __launch_bounds__(256, 2) void gemm_tf32mma(
    const float* __restrict__ A, const float* __restrict__ Bw,
    const float* __restrict__ bias, float* __restrict__ C,
    int N, int K)
{
    __shared__ float As[2][16][PITCH];
    __shared__ float Bs[2][16][PITCH];

    const int t    = threadIdx.x;
    const int bx   = blockIdx.x;
    const int by   = blockIdx.y;
    const int lane = t & 31;
    const int w    = t >> 5;
    const int wm   = w & 3;
    const int wn   = w >> 2;
    const int gid  = lane >> 2;
    const int tig  = lane & 3;

    const float* Ab = A  + (size_t)(by * 128) * K;
    const float* Bb = Bw + (size_t)(bx * 128) * K;

    const int lm = t & 127;
    const int f0 = (t >> 7) * 2;

    float acc[2][8][4];
#pragma unroll
    for (int i = 0; i < 2; i++)
#pragma unroll
        for (int jx = 0; jx < 8; jx++)
#pragma unroll
            for (int q = 0; q < 4; q++) acc[i][jx][q] = 0.0f;

    float4 pa[2], pb[2];
#pragma unroll
    for (int r = 0; r < 2; r++) {
        pa[r] = *(const float4*)(Ab + (size_t)lm * K + (f0 + r) * 4);
        pb[r] = *(const float4*)(Bb + (size_t)lm * K + (f0 + r) * 4);
    }
#pragma unroll
    for (int r = 0; r < 2; r++) {
        const int kk = (f0 + r) * 4;
        As[0][kk + 0][lm] = f2tf32(pa[r].x);
        As[0][kk + 1][lm] = f2tf32(pa[r].y);
        As[0][kk + 2][lm] = f2tf32(pa[r].z);
        As[0][kk + 3][lm] = f2tf32(pa[r].w);
        Bs[0][kk + 0][lm] = f2tf32(pb[r].x);
        Bs[0][kk + 1][lm] = f2tf32(pb[r].y);
        Bs[0][kk + 2][lm] = f2tf32(pb[r].z);
        Bs[0][kk + 3][lm] = f2tf32(pb[r].w);
    }
    __syncthreads();

    const int nst = K >> 4;
    for (int s = 0; s < nst; s++) {
        const int cur = s & 1;
        const bool pf = (s + 1 < nst);
        if (pf) {
            const int kbase = (s + 1) * 16;
#pragma unroll
            for (int r = 0; r < 2; r++) {
                pa[r] = *(const float4*)(Ab + (size_t)lm * K + kbase + (f0 + r) * 4);
                pb[r] = *(const float4*)(Bb + (size_t)lm * K + kbase + (f0 + r) * 4);
            }
        }
#pragma unroll
        for (int kk = 0; kk < 16; kk += 8) {
            float a[2][4], b[8][2];
#pragma unroll
            for (int i = 0; i < 2; i++) {
                const int m = wm * 32 + i * 16 + gid;
                a[i][0] = As[cur][kk + tig][m];
                a[i][1] = As[cur][kk + tig][m + 8];
                a[i][2] = As[cur][kk + tig + 4][m];
                a[i][3] = As[cur][kk + tig + 4][m + 8];
            }
#pragma unroll
            for (int jx = 0; jx < 8; jx++) {
                const int n = wn * 64 + jx * 8 + gid;
                b[jx][0] = Bs[cur][kk + tig][n];
                b[jx][1] = Bs[cur][kk + tig + 4][n];
            }
#pragma unroll
            for (int i = 0; i < 2; i++)
#pragma unroll
                for (int jx = 0; jx < 8; jx++)
                    mma_tf32(acc[i][jx], a[i], b[jx]);
        }
        if (pf) {
            const int nxt = cur ^ 1;
#pragma unroll
            for (int r = 0; r < 2; r++) {
                const int kk = (f0 + r) * 4;
                As[nxt][kk + 0][lm] = f2tf32(pa[r].x);
                As[nxt][kk + 1][lm] = f2tf32(pa[r].y);
                As[nxt][kk + 2][lm] = f2tf32(pa[r].z);
                As[nxt][kk + 3][lm] = f2tf32(pa[r].w);
                Bs[nxt][kk + 0][lm] = f2tf32(pb[r].x);
                Bs[nxt][kk + 1][lm] = f2tf32(pb[r].y);
                Bs[nxt][kk + 2][lm] = f2tf32(pb[r].z);
                Bs[nxt][kk + 3][lm] = f2tf32(pb[r].w);
            }
        }
        __syncthreads();
    }

#pragma unroll
    for (int i = 0; i < 2; i++) {
        const int m0 = by * 128 + wm * 32 + i * 16 + gid;
#pragma unroll
        for (int jx = 0; jx < 8; jx++) {
            const int n = bx * 128 + wn * 64 + jx * 8 + tig * 2;
            const float b0 = __ldg(bias + n);
            const float b1 = __ldg(bias + n + 1);
            float2 v0, v1;
            v0.x = acc[i][jx][0] + b0;  v0.y = acc[i][jx][1] + b1;
            v1.x = acc[i][jx][2] + b0;  v1.y = acc[i][jx][3] + b1;
            *(float2*)(C + (size_t)m0 * N + n)       = v0;
            *(float2*)(C + (size_t)(m0 + 8) * N + n) = v1;
        }
    }
}

// =============================================================================
// HMMA persistent GRU recurrence, v5: cluster-8, 2 CTAs/SM.
//  32 clusters x 8 CTAs (grid 256), 8 batch rows per cluster.
//  CTA rank owns hidden cols [r*32, r*32+32) = 96 gate rows of W_hh in regs
//  (6 warps x 16 rows; same 128 frag regs/thread). 192 threads/CTA ->
//  per-CTA regfile ~32K -> TWO co-resident CTAs from DIFFERENT clusters per
//  SM, giving two independent recurrence chains to interleave (round-10 ncu:
//  issue 14.6%, all pipes <15% => single-chain latency bound at 1 CTA/SM).
//  Numerics identical to rounds 6/10 (rel_err ~3.0e-4).
// =============================================================================
#define HP 9
#define OFF_HBUF(par) ((par) * (256 * HP))              // 2 x 2304
#define OFF_GH        (2 * 256 * HP)                    // 4608, 8x104 = 832
#define OFF_GIS(par)  (2 * 256 * HP + 832 + (par) * 768)
#define OFF_BHH       (2 * 256 * HP + 832 + 2 * 768)    // 96
#define OFF_MBAR      (OFF_BHH + 96)                    // 8B aligned (x4 -> /8 ok)
#define REC_SMEM_BYTES ((OFF_MBAR + 4) * 4)

__global__ void __cluster_dims__(8, 1, 1) __launch_bounds__(192, 2)
gru_rec_mma(const float* __restrict__ Whh, const float* __restrict__ bhh_g,
            const float* __restrict__ gi, float* __restrict__ hout,
            int store_all)
{
    extern __shared__ float smf[];
    float* bhh = smf + OFF_BHH;
    float* gh  = smf + OFF_GH;
    const uint32_t mbar = (uint32_t)__cvta_generic_to_shared(smf + OFF_MBAR);

    cg::cluster_group cluster = cg::this_cluster();
    const int rank = cluster.block_rank();        // 0..7
    const int B0   = (blockIdx.x >> 3) * 8;       // 8 batch rows per cluster

    const int t    = threadIdx.x;                 // 0..191
    const int lane = t & 31;
    const int w    = t >> 5;              // 0..5
    const int gid  = lane >> 2;           // 0..7
    const int tig  = lane & 3;            // 0..3

    // ---- W_hh fragments -> registers (once): warp w owns m-tile w of 96 rows
    float wa0[32], wa1[32], wa2[32], wa3[32];
    {
        const int g  = w >> 1;                                // gate 0..2
        const int r0 = g * 256 + rank * 32 + (w & 1) * 16 + gid;
        const float* p0 = Whh + (size_t)r0 * 256;
        const float* p1 = p0 + 8 * 256;
#pragma unroll
        for (int s = 0; s < 32; s++) {
            wa0[s] = f2tf32(p0[8 * s + tig]);
            wa1[s] = f2tf32(p1[8 * s + tig]);
            wa2[s] = f2tf32(p0[8 * s + tig + 4]);
            wa3[s] = f2tf32(p1[8 * s + tig + 4]);
        }
    }
    for (int i = t; i < 96; i += 192)
        bhh[i] = bhh_g[(i >> 5) * 256 + rank * 32 + (i & 31)];
    for (int i = t; i < 2 * 256 * HP; i += 192) smf[i] = 0.0f;   // zero hbufs
    if (t == 0) MBAR_INIT(mbar, 8);
    __syncthreads();
    cluster.sync();                         // mbar + zeroed hbufs visible
    if (t < 8) MBAR_ARRIVE_RANK(mbar, t);   // prime phase 0: h(0) "ready"

    // gate-phase identity (threads 0..127): pairs (j, bb) and (j, bb+4)
    const int j     = t & 31;
    const int bb    = (t >> 5) & 3;
    const int kglob = rank * 32 + j;
    float hprev0 = 0.0f, hprev1 = 0.0f;     // exact fp32 state

    // cp.async chunk identity (192 threads x 16B = 768 floats = 8 x 96)
    const int cb   = t / 24;              // batch 0..7
    const int crem = t % 24;
    const int cg_  = crem >> 3;           // gate 0..2
    const int cq   = crem & 7;            // 4-float group 0..7 (32 cols)
    const uint32_t gis_dst0 = (uint32_t)__cvta_generic_to_shared(
        smf + OFF_GIS(0) + cb * 96 + cg_ * 32 + cq * 4);
    const float* gi_src0 = gi + ((size_t)B0 + cb) * G3 + cg_ * 256 + rank * 32 + cq * 4;

    // prologue: gi(0) into gi_s buffer 0
    cp_async16(gis_dst0, gi_src0);
    asm volatile("cp.async.commit_group;" ::: "memory");

    for (int ts = 0; ts < T_STEPS; ts++) {
        const int par = ts & 1;

        // prefetch gi(ts+1) into the other buffer (full step of cover)
        {
            const int tn = (ts + 1 < T_STEPS) ? (ts + 1) : ts;
            cp_async16(gis_dst0 + (par ^ 1) * 768 * 4,
                       gi_src0 + (size_t)tn * BATCH * G3);
            asm volatile("cp.async.commit_group;" ::: "memory");
        }

        MBAR_WAIT(mbar, par);                          // h(ts) visible (all CTAs)

        // ---- GEMM: D[96x8] = W @ h^T, 4 independent chains (depth 8) ----
        {
            float c0[4] = {0, 0, 0, 0}, c1[4] = {0, 0, 0, 0};
            float c2[4] = {0, 0, 0, 0}, c3[4] = {0, 0, 0, 0};
            const float* hb = smf + OFF_HBUF(par) + tig * HP + gid;
#pragma unroll
            for (int s = 0; s < 32; s += 4) {
                float b0[2] = { hb[(s + 0) * 8 * HP], hb[(s + 0) * 8 * HP + 4 * HP] };
                float b1[2] = { hb[(s + 1) * 8 * HP], hb[(s + 1) * 8 * HP + 4 * HP] };
                float b2[2] = { hb[(s + 2) * 8 * HP], hb[(s + 2) * 8 * HP + 4 * HP] };
                float b3[2] = { hb[(s + 3) * 8 * HP], hb[(s + 3) * 8 * HP + 4 * HP] };
                float w0[4] = { wa0[s + 0], wa1[s + 0], wa2[s + 0], wa3[s + 0] };
                float w1[4] = { wa0[s + 1], wa1[s + 1], wa2[s + 1], wa3[s + 1] };
                float w2[4] = { wa0[s + 2], wa1[s + 2], wa2[s + 2], wa3[s + 2] };
                float w3[4] = { wa0[s + 3], wa1[s + 3], wa2[s + 3], wa3[s + 3] };
                mma_tf32(c0, w0, b0);
                mma_tf32(c1, w1, b1);
                mma_tf32(c2, w2, b2);
                mma_tf32(c3, w3, b3);
            }
            const int lr = w * 16 + gid;          // 0..95
            const int bi = tig * 2;
            gh[(bi    ) * 104 + lr    ] = (c0[0] + c1[0]) + (c2[0] + c3[0]);
            gh[(bi + 1) * 104 + lr    ] = (c0[1] + c1[1]) + (c2[1] + c3[1]);
            gh[(bi    ) * 104 + lr + 8] = (c0[2] + c1[2]) + (c2[2] + c3[2]);
            gh[(bi + 1) * 104 + lr + 8] = (c0[3] + c1[3]) + (c2[3] + c3[3]);
        }
        // per-thread wait for gi(ts), ALL threads, BEFORE the barrier
        asm volatile("cp.async.wait_group 1;" ::: "memory");
        __syncthreads();                               // gh + gi_s[par] ready

        // ---- gates + exact-register h update + tf32 DSMEM broadcast ----
        if (t < 128) {
            const float* gis = smf + OFF_GIS(par);
            float* hwr = smf + OFF_HBUF(par ^ 1);
            const float br = bhh[j], bz = bhh[32 + j], bn = bhh[64 + j];
#pragma unroll
            for (int i = 0; i < 2; i++) {
                const int b = bb + 4 * i;
                const float hr = gh[b * 104 + j]      + br;
                const float hz = gh[b * 104 + 32 + j] + bz;
                const float hn = gh[b * 104 + 64 + j] + bn;
                const float ir  = gis[b * 96 + j];
                const float iz  = gis[b * 96 + 32 + j];
                const float in_ = gis[b * 96 + 64 + j];
                const float r = __fdividef(1.0f, 1.0f + __expf(-(ir + hr)));
                const float z = __fdividef(1.0f, 1.0f + __expf(-(iz + hz)));
                const float n = tanh_fast(in_ + r * hn);
                const float hprev = (i == 0) ? hprev0 : hprev1;
                const float hnew  = (1.0f - z) * n + z * hprev;
                if (i == 0) hprev0 = hnew; else hprev1 = hnew;

                const float hop = f2tf32(hnew);
                float* lp = hwr + kglob * HP + b;
#pragma unroll
                for (int q = 0; q < 8; q++)
                    *(float*)cluster.map_shared_rank(lp, q) = hop;

                if (store_all) {
                    hout[((size_t)ts * BATCH + B0 + b) * HID + kglob] = hnew;
                } else if (ts == T_STEPS - 1) {
                    hout[(size_t)(B0 + b) * HID + kglob] = hnew;
                }
            }
        }
        __syncthreads();                     // all gates stores issued CTA-wide
        if (t < 8) MBAR_ARRIVE_RANK(mbar, t);          // signal h(ts+1) ready
    }

    // REQUIRED: no CTA may exit while peers can still DSMEM-store into its
    // SMEM (final step's gates writes).
    cluster.sync();
}

// =============================================================================
// FC on the last hidden state
// =============================================================================
__global__ __launch_bounds__(256) void fc_kernel(
    const float* __restrict__ Wfc, const float* __restrict__ bfc,
    float* __restrict__ out)
{
    __shared__ float hs[256];
    const int b = blockIdx.x;
    const int o = threadIdx.x;
    hs[o] = g_h2[b * 256 + o];
    __syncthreads();
    const float* wr = Wfc + (size_t)o * 256;
    float acc = 0.0f;
#pragma unroll 8
    for (int k = 0; k < 256; k += 4) {
        const float4 wv = *(const float4*)(wr + k);
        acc += hs[k] * wv.x + hs[k + 1] * wv.y + hs[k + 2] * wv.z + hs[k + 3] * wv.w;
    }
    out[b * 256 + o] = acc + bfc[o];
}

// =============================================================================
extern "C" void kernel_launch(void* const* d_in, const int* in_sizes, int n_in,
                              void* d_out, int out_size)
{
    const float* x     = (const float*)d_in[0];
    const float* W_ih0 = (const float*)d_in[1];
    const float* W_hh0 = (const float*)d_in[2];
    const float* b_ih0 = (const float*)d_in[3];
    const float* b_hh0 = (const float*)d_in[4];
    const float* W_ih1 = (const float*)d_in[5];
    const float* W_hh1 = (const float*)d_in[6];
    const float* b_ih1 = (const float*)d_in[7];
    const float* b_hh1 = (const float*)d_in[8];
    const float* W_fc  = (const float*)d_in[9];
    const float* b_fc  = (const float*)d_in[10];
    float* out = (float*)d_out;

    float *gi_p, *h1_p, *h2_p;
    cudaGetSymbolAddress((void**)&gi_p, g_gi);
    cudaGetSymbolAddress((void**)&h1_p, g_h1);
    cudaGetSymbolAddress((void**)&h2_p, g_h2);

    cudaFuncSetAttribute(gru_rec_mma, cudaFuncAttributeMaxDynamicSharedMemorySize,
                         REC_SMEM_BYTES);

    const int M = T_STEPS * BATCH;        // 131072
    dim3 gemm_grid(G3 / 128, M / 128);    // (6, 1024)

    // layer 0: gi0 = x @ W_ih0^T + b_ih0   (tf32 HMMA, K=128)
    gemm_tf32mma<<<gemm_grid, 256>>>(x, W_ih0, b_ih0, gi_p, G3, IN0);
    // layer 0 recurrence -> g_h1[T,B,H]   (32 clusters x 8 CTAs, 2 CTAs/SM)
    gru_rec_mma<<<256, 192, REC_SMEM_BYTES>>>(W_hh0, b_hh0, gi_p, h1_p, 1);
    // layer 1: gi1 = h1 @ W_ih1^T + b_ih1  (tf32 HMMA, K=256)
    gemm_tf32mma<<<gemm_grid, 256>>>(h1_p, W_ih1, b_ih1, gi_p, G3, HID);
    // layer 1 recurrence -> g_h2[B,H]
    gru_rec_mma<<<256, 192, REC_SMEM_BYTES>>>(W_hh1, b_hh1, gi_p, h2_p, 0);
    // FC head
    fc_kernel<<<BATCH, 256>>>(W_fc, b_fc, out);
}

// round 12
// speedup vs baseline: 1.2147x; 1.2147x over previous
#include <cuda_runtime.h>
#include <cooperative_groups.h>
#include <cstdint>

namespace cg = cooperative_groups;

#define T_STEPS 512
#define BATCH   256
#define IN0     128
#define HID     256
#define G3      768   // 3*HID

// ---------------- scratch (static device arrays; allocation-free) ------------
__device__ float g_gi[(size_t)T_STEPS * BATCH * G3];   // reused by both layers
__device__ float g_h1[(size_t)T_STEPS * BATCH * HID];  // layer-0 outputs
__device__ float g_h2[BATCH * HID];                    // final hidden state

// ======================= helpers ========================
__device__ __forceinline__ float f2tf32(float x) {
    float r;
    asm("cvt.rna.tf32.f32 %0, %1;" : "=f"(r) : "f"(x));
    return r;
}

__device__ __forceinline__ void mma_tf32(float* d, const float* a, const float* b) {
    asm volatile(
        "mma.sync.aligned.m16n8k8.row.col.f32.tf32.tf32.f32 "
        "{%0,%1,%2,%3}, {%4,%5,%6,%7}, {%8,%9}, {%0,%1,%2,%3};"
        : "+f"(d[0]), "+f"(d[1]), "+f"(d[2]), "+f"(d[3])
        : "r"(__float_as_uint(a[0])), "r"(__float_as_uint(a[1])),
          "r"(__float_as_uint(a[2])), "r"(__float_as_uint(a[3])),
          "r"(__float_as_uint(b[0])), "r"(__float_as_uint(b[1])));
}

__device__ __forceinline__ void cp_async16(uint32_t dst, const void* src) {
    asm volatile("cp.async.cg.shared.global [%0], [%1], 16;"
                 :: "r"(dst), "l"(src) : "memory");
}

__device__ __forceinline__ float tanh_fast(float x) {
    float r;
    asm("tanh.approx.f32 %0, %1;" : "=f"(r) : "f"(x));
    return r;
}

#define MBAR_INIT(addr, cnt) \
    asm volatile("mbarrier.init.shared.b64 [%0], %1;" \
                 :: "r"((uint32_t)(addr)), "r"((uint32_t)(cnt)) : "memory")

#define MBAR_ARRIVE_RANK(local_addr, rk)                                        \
    asm volatile("{\n\t.reg .b32 ra;\n\t"                                       \
        "mapa.shared::cluster.u32 ra, %0, %1;\n\t"                              \
        "mbarrier.arrive.release.cluster.shared::cluster.b64 _, [ra];\n\t}"     \
        :: "r"((uint32_t)(local_addr)), "r"((uint32_t)(rk)) : "memory")

#define MBAR_WAIT(addr, par) do {                                               \
    uint32_t _m = (uint32_t)(addr); uint32_t _p = (uint32_t)(par); uint32_t _d; \
    asm volatile("{\n\t.reg .pred p;\n\t"                                       \
        "mbarrier.try_wait.parity.acquire.cluster.shared::cta.b64 p, [%1], %2;\n\t" \
        "selp.b32 %0, 1, 0, p;\n\t}"                                            \
        : "=r"(_d) : "r"(_m), "r"(_p) : "memory");                              \
    if (!_d) {                                                                  \
        asm volatile("{\n\t.reg .pred P1;\n\t"                                  \
            "WL_%=:\n\t"                                                        \
            "mbarrier.try_wait.parity.acquire.cluster.shared::cta.b64 P1, [%0], %1, 0x989680;\n\t" \
            "@P1 bra.uni WD_%=;\n\t"                                            \
            "bra.uni WL_%=;\n\t"                                                \
            "WD_%=:\n\t}"                                                       \
            :: "r"(_m), "r"(_p) : "memory");                                    \
    }                                                                           \
} while (0)

// =============================================================================
// HMMA tf32 GEMM:  C[M,N] = A[M,K] @ Bw[N,K]^T + bias[N]   (validated R4)
// =============================================================================
#define PITCH 136

__global__ __launch_bounds__(256, 2) void gemm_tf32mma(
    const float* __restrict__ A, const float* __restrict__ Bw,
    const float* __restrict__ bias, float* __restrict__ C,
    int N, int K)
{
    __shared__ float As[2][16][PITCH];
    __shared__ float Bs[2][16][PITCH];

    const int t    = threadIdx.x;
    const int bx   = blockIdx.x;
    const int by   = blockIdx.y;
    const int lane = t & 31;
    const int w    = t >> 5;
    const int wm   = w & 3;
    const int wn   = w >> 2;
    const int gid  = lane >> 2;
    const int tig  = lane & 3;

    const float* Ab = A  + (size_t)(by * 128) * K;
    const float* Bb = Bw + (size_t)(bx * 128) * K;

    const int lm = t & 127;
    const int f0 = (t >> 7) * 2;

    float acc[2][8][4];
#pragma unroll
    for (int i = 0; i < 2; i++)
#pragma unroll
        for (int jx = 0; jx < 8; jx++)
#pragma unroll
            for (int q = 0; q < 4; q++) acc[i][jx][q] = 0.0f;

    float4 pa[2], pb[2];
#pragma unroll
    for (int r = 0; r < 2; r++) {
        pa[r] = *(const float4*)(Ab + (size_t)lm * K + (f0 + r) * 4);
        pb[r] = *(const float4*)(Bb + (size_t)lm * K + (f0 + r) * 4);
    }
#pragma unroll
    for (int r = 0; r < 2; r++) {
        const int kk = (f0 + r) * 4;
        As[0][kk + 0][lm] = f2tf32(pa[r].x);
        As[0][kk + 1][lm] = f2tf32(pa[r].y);
        As[0][kk + 2][lm] = f2tf32(pa[r].z);
        As[0][kk + 3][lm] = f2tf32(pa[r].w);
        Bs[0][kk + 0][lm] = f2tf32(pb[r].x);
        Bs[0][kk + 1][lm] = f2tf32(pb[r].y);
        Bs[0][kk + 2][lm] = f2tf32(pb[r].z);
        Bs[0][kk + 3][lm] = f2tf32(pb[r].w);
    }
    __syncthreads();

    const int nst = K >> 4;
    for (int s = 0; s < nst; s++) {
        const int cur = s & 1;
        const bool pf = (s + 1 < nst);
        if (pf) {
            const int kbase = (s + 1) * 16;
#pragma unroll
            for (int r = 0; r < 2; r++) {
                pa[r] = *(const float4*)(Ab + (size_t)lm * K + kbase + (f0 + r) * 4);
                pb[r] = *(const float4*)(Bb + (size_t)lm * K + kbase + (f0 + r) * 4);
            }
        }
#pragma unroll
        for (int kk = 0; kk < 16; kk += 8) {
            float a[2][4], b[8][2];
#pragma unroll
            for (int i = 0; i < 2; i++) {
                const int m = wm * 32 + i * 16 + gid;
                a[i][0] = As[cur][kk + tig][m];
                a[i][1] = As[cur][kk + tig][m + 8];
                a[i][2] = As[cur][kk + tig + 4][m];
                a[i][3] = As[cur][kk + tig + 4][m + 8];
            }
#pragma unroll
            for (int jx = 0; jx < 8; jx++) {
                const int n = wn * 64 + jx * 8 + gid;
                b[jx][0] = Bs[cur][kk + tig][n];
                b[jx][1] = Bs[cur][kk + tig + 4][n];
            }
#pragma unroll
            for (int i = 0; i < 2; i++)
#pragma unroll
                for (int jx = 0; jx < 8; jx++)
                    mma_tf32(acc[i][jx], a[i], b[jx]);
        }
        if (pf) {
            const int nxt = cur ^ 1;
#pragma unroll
            for (int r = 0; r < 2; r++) {
                const int kk = (f0 + r) * 4;
                As[nxt][kk + 0][lm] = f2tf32(pa[r].x);
                As[nxt][kk + 1][lm] = f2tf32(pa[r].y);
                As[nxt][kk + 2][lm] = f2tf32(pa[r].z);
                As[nxt][kk + 3][lm] = f2tf32(pa[r].w);
                Bs[nxt][kk + 0][lm] = f2tf32(pb[r].x);
                Bs[nxt][kk + 1][lm] = f2tf32(pb[r].y);
                Bs[nxt][kk + 2][lm] = f2tf32(pb[r].z);
                Bs[nxt][kk + 3][lm] = f2tf32(pb[r].w);
            }
        }
        __syncthreads();
    }

#pragma unroll
    for (int i = 0; i < 2; i++) {
        const int m0 = by * 128 + wm * 32 + i * 16 + gid;
#pragma unroll
        for (int jx = 0; jx < 8; jx++) {
            const int n = bx * 128 + wn * 64 + jx * 8 + tig * 2;
            const float b0 = __ldg(bias + n);
            const float b1 = __ldg(bias + n + 1);
            float2 v0, v1;
            v0.x = acc[i][jx][0] + b0;  v0.y = acc[i][jx][1] + b1;
            v1.x = acc[i][jx][2] + b0;  v1.y = acc[i][jx][3] + b1;
            *(float2*)(C + (size_t)m0 * N + n)       = v0;
            *(float2*)(C + (size_t)(m0 + 8) * N + n) = v1;
        }
    }
}

// =============================================================================
// GRU recurrence v6: SMEM-resident W, 24 warps, throughput-bound step.
//  32 clusters x 4 CTAs (grid 128), 8 batch/cluster, rank owns 64 hidden cols
//  (192 gate rows). W_hh slice lives in SMEM as tf32 (196.6KB), XOR-swizzled
//  (k ^ ((row&7)<<2), pitch 256 -> conflict-free A-frag loads). 24 warps:
//  warp (tile, khalf) computes 16 rows x 8 batch x 128 k (4 chains, depth 4).
//  K-halves merged in SMEM 'part' (doubles as gh). Registers freed (~85/thr)
//  so 6 warps/SMSP hide MMA/LDS/sync latency; floor = W-stream 196.6KB /
//  128 B/cyc ~ 1536 cyc/step vs measured 5700 in the reg-resident design.
//  Sync skeleton (mbar count=4, DSMEM h broadcast) identical to round 10.
// =============================================================================
#define HP 9
#define OFF_WT    0                          // 192*256 = 49152 floats
#define OFF_HBUF  49152                      // 2 * 256*HP = 4608
#define OFF_PART  (49152 + 2 * 256 * HP)     // 53760; 12 tiles * 144 = 1728
#define OFF_GIS   (OFF_PART + 12 * 144)      // 55488; 1536
#define OFF_BHH   (OFF_GIS + 1536)           // 57024; 192
#define OFF_MBAR  (OFF_BHH + 192)            // 57216 (8B-aligned byte addr)
#define REC_SMEM_BYTES ((OFF_MBAR + 4) * 4)  // 228,880 B  (< 232,448 cap)

__global__ void __cluster_dims__(4, 1, 1) __launch_bounds__(768, 1)
gru_rec_smem(const float* __restrict__ Whh, const float* __restrict__ bhh_g,
             const float* __restrict__ gi, float* __restrict__ hout,
             int store_all)
{
    extern __shared__ float smf[];
    float* Wt   = smf + OFF_WT;
    float* part = smf + OFF_PART;
    float* gis  = smf + OFF_GIS;
    float* bhh  = smf + OFF_BHH;
    const uint32_t mbar = (uint32_t)__cvta_generic_to_shared(smf + OFF_MBAR);

    cg::cluster_group cluster = cg::this_cluster();
    const int rank = cluster.block_rank();
    const int B0   = (blockIdx.x >> 2) * 8;

    const int t    = threadIdx.x;                 // 0..767
    const int lane = t & 31;
    const int w    = t >> 5;              // 0..23
    const int gid  = lane >> 2;           // 0..7
    const int tig  = lane & 3;            // 0..3
    const int tile = w >> 1;              // 0..11
    const int kh   = w & 1;               // k-half

    // ---- one-time: W slice -> SMEM (tf32, swizzled), biases, zero hbuf ----
    for (int i = t; i < 192 * 256; i += 768) {
        const int rr = i >> 8;
        const int k  = i & 255;
        const int grow = ((rr >> 6) << 8) + rank * 64 + (rr & 63);
        Wt[(rr << 8) + (k ^ ((rr & 7) << 2))] = f2tf32(Whh[(size_t)grow * 256 + k]);
    }
    for (int i = t; i < 192; i += 768)
        bhh[i] = bhh_g[((i >> 6) << 8) + rank * 64 + (i & 63)];
    for (int i = t; i < 2 * 256 * HP; i += 768) smf[OFF_HBUF + i] = 0.0f;
    if (t == 0) MBAR_INIT(mbar, 4);
    __syncthreads();
    cluster.sync();
    if (t < 4) MBAR_ARRIVE_RANK(mbar, t);   // prime phase 0

    // gate-phase identity (threads 0..255)
    const int j     = t & 63;
    const int bb    = (t >> 6) & 3;
    const int kglob = rank * 64 + j;
    float hprev0 = 0.0f, hprev1 = 0.0f;

    // cp.async identity: threads 0..383 move 16B each (1536 floats total)
    const int cb   = t / 48;
    const int crem = t % 48;
    const int cg_  = crem >> 4;
    const int cq   = crem & 15;
    const uint32_t gis_dst = (uint32_t)__cvta_generic_to_shared(
        gis + cb * 192 + cg_ * 64 + cq * 4);
    const float* gi_src = gi + ((size_t)B0 + cb) * G3 + cg_ * 256 + rank * 64 + cq * 4;

    // GEMM constants
    const int xg    = gid << 2;
    const int base0 = (tile * 16 + gid) << 8;
    const int base1 = base0 + (8 << 8);
    const int khb   = kh * 128;
    const int pa0   = tile * 144 + gid * 9 + tig * 2;        // part (row gid)
    const int pa8   = tile * 144 + (gid + 8) * 9 + tig * 2;  // part (row gid+8)

    for (int ts = 0; ts < T_STEPS; ts++) {
        const int par = ts & 1;

        MBAR_WAIT(mbar, par);                          // h(ts) visible

        // gi(ts) -> SMEM (consumed ~after GEMM; latency covered)
        if (t < 384) {
            cp_async16(gis_dst, gi_src + (size_t)ts * BATCH * G3);
        }
        asm volatile("cp.async.commit_group;" ::: "memory");

        // ---- GEMM: partial D[16x8] over this warp's 128-k half ----
        float c0[4] = {0, 0, 0, 0}, c1[4] = {0, 0, 0, 0};
        float c2[4] = {0, 0, 0, 0}, c3[4] = {0, 0, 0, 0};
        {
            const float* hb = smf + OFF_HBUF + par * (256 * HP) + gid;
#pragma unroll
            for (int s = 0; s < 16; s += 4) {
#pragma unroll
                for (int u = 0; u < 4; u++) {
                    const int k0 = khb + ((s + u) << 3);
                    const int i0 = (k0 | tig) ^ xg;
                    const int i4 = (k0 | (tig + 4)) ^ xg;
                    float a[4], b[2];
                    a[0] = Wt[base0 + i0];
                    a[1] = Wt[base1 + i0];
                    a[2] = Wt[base0 + i4];
                    a[3] = Wt[base1 + i4];
                    b[0] = hb[(k0 + tig) * HP];
                    b[1] = hb[(k0 + tig + 4) * HP];
                    if (u == 0)      mma_tf32(c0, a, b);
                    else if (u == 1) mma_tf32(c1, a, b);
                    else if (u == 2) mma_tf32(c2, a, b);
                    else             mma_tf32(c3, a, b);
                }
            }
        }
        float d0 = (c0[0] + c1[0]) + (c2[0] + c3[0]);
        float d1 = (c0[1] + c1[1]) + (c2[1] + c3[1]);
        float d2 = (c0[2] + c1[2]) + (c2[2] + c3[2]);
        float d3 = (c0[3] + c1[3]) + (c2[3] + c3[3]);

        // ---- k-half merge through 'part' (doubles as gh) ----
        if (kh == 1) {
            part[pa0] = d0; part[pa0 + 1] = d1;
            part[pa8] = d2; part[pa8 + 1] = d3;
        }
        __syncthreads();                               // bar A
        if (kh == 0) {
            d0 += part[pa0]; d1 += part[pa0 + 1];
            d2 += part[pa8]; d3 += part[pa8 + 1];
            part[pa0] = d0; part[pa0 + 1] = d1;
            part[pa8] = d2; part[pa8 + 1] = d3;
        }
        asm volatile("cp.async.wait_group 0;" ::: "memory");  // all threads
        __syncthreads();                               // bar B: gh + gi ready

        // ---- gates + exact-register h update + tf32 DSMEM broadcast ----
        if (t < 256) {
            float* hwr = smf + OFF_HBUF + (par ^ 1) * (256 * HP);
            const float br = bhh[j], bz = bhh[64 + j], bn = bhh[128 + j];
            const int tj = (j >> 4) * 144 + (j & 15) * 9;
#pragma unroll
            for (int i = 0; i < 2; i++) {
                const int b = bb + 4 * i;
                const float hr = part[tj + b]           + br;   // gate r rows 0..63
                const float hz = part[4 * 144 + tj + b] + bz;   // gate z rows 64..127
                const float hn = part[8 * 144 + tj + b] + bn;   // gate n rows 128..191
                const float ir  = gis[b * 192 + j];
                const float iz  = gis[b * 192 + 64 + j];
                const float in_ = gis[b * 192 + 128 + j];
                const float r = __fdividef(1.0f, 1.0f + __expf(-(ir + hr)));
                const float z = __fdividef(1.0f, 1.0f + __expf(-(iz + hz)));
                const float n = tanh_fast(in_ + r * hn);
                const float hprev = (i == 0) ? hprev0 : hprev1;
                const float hnew  = (1.0f - z) * n + z * hprev;
                if (i == 0) hprev0 = hnew; else hprev1 = hnew;

                const float hop = f2tf32(hnew);
                float* lp = hwr + kglob * HP + b;
#pragma unroll
                for (int q = 0; q < 4; q++)
                    *(float*)cluster.map_shared_rank(lp, q) = hop;

                if (store_all) {
                    hout[((size_t)ts * BATCH + B0 + b) * HID + kglob] = hnew;
                } else if (ts == T_STEPS - 1) {
                    hout[(size_t)(B0 + b) * HID + kglob] = hnew;
                }
            }
        }
        __syncthreads();                               // bar C
        if (t < 4) MBAR_ARRIVE_RANK(mbar, t);          // signal h(ts+1) ready
    }

    // no CTA may exit while peers can still DSMEM-store into its SMEM
    cluster.sync();
}

// =============================================================================
// FC on the last hidden state
// =============================================================================
__global__ __launch_bounds__(256) void fc_kernel(
    const float* __restrict__ Wfc, const float* __restrict__ bfc,
    float* __restrict__ out)
{
    __shared__ float hs[256];
    const int b = blockIdx.x;
    const int o = threadIdx.x;
    hs[o] = g_h2[b * 256 + o];
    __syncthreads();
    const float* wr = Wfc + (size_t)o * 256;
    float acc = 0.0f;
#pragma unroll 8
    for (int k = 0; k < 256; k += 4) {
        const float4 wv = *(const float4*)(wr + k);
        acc += hs[k] * wv.x + hs[k + 1] * wv.y + hs[k + 2] * wv.z + hs[k + 3] * wv.w;
    }
    out[b * 256 + o] = acc + bfc[o];
}

// =============================================================================
extern "C" void kernel_launch(void* const* d_in, const int* in_sizes, int n_in,
                              void* d_out, int out_size)
{
    const float* x     = (const float*)d_in[0];
    const float* W_ih0 = (const float*)d_in[1];
    const float* W_hh0 = (const float*)d_in[2];
    const float* b_ih0 = (const float*)d_in[3];
    const float* b_hh0 = (const float*)d_in[4];
    const float* W_ih1 = (const float*)d_in[5];
    const float* W_hh1 = (const float*)d_in[6];
    const float* b_ih1 = (const float*)d_in[7];
    const float* b_hh1 = (const float*)d_in[8];
    const float* W_fc  = (const float*)d_in[9];
    const float* b_fc  = (const float*)d_in[10];
    float* out = (float*)d_out;

    float *gi_p, *h1_p, *h2_p;
    cudaGetSymbolAddress((void**)&gi_p, g_gi);
    cudaGetSymbolAddress((void**)&h1_p, g_h1);
    cudaGetSymbolAddress((void**)&h2_p, g_h2);

    cudaFuncSetAttribute(gru_rec_smem, cudaFuncAttributeMaxDynamicSharedMemorySize,
                         REC_SMEM_BYTES);

    const int M = T_STEPS * BATCH;        // 131072
    dim3 gemm_grid(G3 / 128, M / 128);    // (6, 1024)

    // layer 0: gi0 = x @ W_ih0^T + b_ih0   (tf32 HMMA, K=128)
    gemm_tf32mma<<<gemm_grid, 256>>>(x, W_ih0, b_ih0, gi_p, G3, IN0);
    // layer 0 recurrence -> g_h1[T,B,H]   (32 clusters x 4 CTAs, SMEM-W, 24 warps)
    gru_rec_smem<<<128, 768, REC_SMEM_BYTES>>>(W_hh0, b_hh0, gi_p, h1_p, 1);
    // layer 1: gi1 = h1 @ W_ih1^T + b_ih1  (tf32 HMMA, K=256)
    gemm_tf32mma<<<gemm_grid, 256>>>(h1_p, W_ih1, b_ih1, gi_p, G3, HID);
    // layer 1 recurrence -> g_h2[B,H]
    gru_rec_smem<<<128, 768, REC_SMEM_BYTES>>>(W_hh1, b_hh1, gi_p, h2_p, 0);
    // FC head
    fc_kernel<<<BATCH, 256>>>(W_fc, b_fc, out);
}

// round 13
// speedup vs baseline: 2.3263x; 1.9151x over previous
#include <cuda_runtime.h>
#include <cooperative_groups.h>
#include <cstdint>

namespace cg = cooperative_groups;

#define T_STEPS 512
#define BATCH   256
#define IN0     128
#define HID     256
#define G3      768   // 3*HID

// ---------------- scratch (static device arrays; allocation-free) ------------
__device__ float g_gi[(size_t)T_STEPS * BATCH * G3];   // reused by both layers
__device__ float g_h1[(size_t)T_STEPS * BATCH * HID];  // layer-0 outputs
__device__ float g_h2[BATCH * HID];                    // final hidden state

// ======================= helpers ========================
__device__ __forceinline__ float f2tf32(float x) {
    float r;
    asm("cvt.rna.tf32.f32 %0, %1;" : "=f"(r) : "f"(x));
    return r;
}

__device__ __forceinline__ void mma_tf32(float* d, const float* a, const float* b) {
    asm volatile(
        "mma.sync.aligned.m16n8k8.row.col.f32.tf32.tf32.f32 "
        "{%0,%1,%2,%3}, {%4,%5,%6,%7}, {%8,%9}, {%0,%1,%2,%3};"
        : "+f"(d[0]), "+f"(d[1]), "+f"(d[2]), "+f"(d[3])
        : "r"(__float_as_uint(a[0])), "r"(__float_as_uint(a[1])),
          "r"(__float_as_uint(a[2])), "r"(__float_as_uint(a[3])),
          "r"(__float_as_uint(b[0])), "r"(__float_as_uint(b[1])));
}

__device__ __forceinline__ void cp_async16(uint32_t dst, const void* src) {
    asm volatile("cp.async.cg.shared.global [%0], [%1], 16;"
                 :: "r"(dst), "l"(src) : "memory");
}

__device__ __forceinline__ float tanh_fast(float x) {
    float r;
    asm("tanh.approx.f32 %0, %1;" : "=f"(r) : "f"(x));
    return r;
}

#define MBAR_INIT(addr, cnt) \
    asm volatile("mbarrier.init.shared.b64 [%0], %1;" \
                 :: "r"((uint32_t)(addr)), "r"((uint32_t)(cnt)) : "memory")

// arrive (release, cluster scope) on rank rk's mbarrier at the same smem offset
#define MBAR_ARRIVE_RANK(local_addr, rk)                                        \
    asm volatile("{\n\t.reg .b32 ra;\n\t"                                       \
        "mapa.shared::cluster.u32 ra, %0, %1;\n\t"                              \
        "mbarrier.arrive.release.cluster.shared::cluster.b64 _, [ra];\n\t}"     \
        :: "r"((uint32_t)(local_addr)), "r"((uint32_t)(rk)) : "memory")

#define MBAR_WAIT(addr, par) do {                                               \
    uint32_t _m = (uint32_t)(addr); uint32_t _p = (uint32_t)(par); uint32_t _d; \
    asm volatile("{\n\t.reg .pred p;\n\t"                                       \
        "mbarrier.try_wait.parity.acquire.cluster.shared::cta.b64 p, [%1], %2;\n\t" \
        "selp.b32 %0, 1, 0, p;\n\t}"                                            \
        : "=r"(_d) : "r"(_m), "r"(_p) : "memory");                              \
    if (!_d) {                                                                  \
        asm volatile("{\n\t.reg .pred P1;\n\t"                                  \
            "WL_%=:\n\t"                                                        \
            "mbarrier.try_wait.parity.acquire.cluster.shared::cta.b64 P1, [%0], %1, 0x989680;\n\t" \
            "@P1 bra.uni WD_%=;\n\t"                                            \
            "bra.uni WL_%=;\n\t"                                                \
            "WD_%=:\n\t}"                                                       \
            :: "r"(_m), "r"(_p) : "memory");                                    \
    }                                                                           \
} while (0)

// =============================================================================
// HMMA tf32 GEMM:  C[M,N] = A[M,K] @ Bw[N,K]^T + bias[N]   (validated R4)
// =============================================================================
#define PITCH 136

__global__ __launch_bounds__(256, 2) void gemm_tf32mma(
    const float* __restrict__ A, const float* __restrict__ Bw,
    const float* __restrict__ bias, float* __restrict__ C,
    int N, int K)
{
    __shared__ float As[2][16][PITCH];
    __shared__ float Bs[2][16][PITCH];

    const int t    = threadIdx.x;
    const int bx   = blockIdx.x;
    const int by   = blockIdx.y;
    const int lane = t & 31;
    const int w    = t >> 5;
    const int wm   = w & 3;
    const int wn   = w >> 2;
    const int gid  = lane >> 2;
    const int tig  = lane & 3;

    const float* Ab = A  + (size_t)(by * 128) * K;
    const float* Bb = Bw + (size_t)(bx * 128) * K;

    const int lm = t & 127;
    const int f0 = (t >> 7) * 2;

    float acc[2][8][4];
#pragma unroll
    for (int i = 0; i < 2; i++)
#pragma unroll
        for (int jx = 0; jx < 8; jx++)
#pragma unroll
            for (int q = 0; q < 4; q++) acc[i][jx][q] = 0.0f;

    float4 pa[2], pb[2];
#pragma unroll
    for (int r = 0; r < 2; r++) {
        pa[r] = *(const float4*)(Ab + (size_t)lm * K + (f0 + r) * 4);
        pb[r] = *(const float4*)(Bb + (size_t)lm * K + (f0 + r) * 4);
    }
#pragma unroll
    for (int r = 0; r < 2; r++) {
        const int kk = (f0 + r) * 4;
        As[0][kk + 0][lm] = f2tf32(pa[r].x);
        As[0][kk + 1][lm] = f2tf32(pa[r].y);
        As[0][kk + 2][lm] = f2tf32(pa[r].z);
        As[0][kk + 3][lm] = f2tf32(pa[r].w);
        Bs[0][kk + 0][lm] = f2tf32(pb[r].x);
        Bs[0][kk + 1][lm] = f2tf32(pb[r].y);
        Bs[0][kk + 2][lm] = f2tf32(pb[r].z);
        Bs[0][kk + 3][lm] = f2tf32(pb[r].w);
    }
    __syncthreads();

    const int nst = K >> 4;
    for (int s = 0; s < nst; s++) {
        const int cur = s & 1;
        const bool pf = (s + 1 < nst);
        if (pf) {
            const int kbase = (s + 1) * 16;
#pragma unroll
            for (int r = 0; r < 2; r++) {
                pa[r] = *(const float4*)(Ab + (size_t)lm * K + kbase + (f0 + r) * 4);
                pb[r] = *(const float4*)(Bb + (size_t)lm * K + kbase + (f0 + r) * 4);
            }
        }
#pragma unroll
        for (int kk = 0; kk < 16; kk += 8) {
            float a[2][4], b[8][2];
#pragma unroll
            for (int i = 0; i < 2; i++) {
                const int m = wm * 32 + i * 16 + gid;
                a[i][0] = As[cur][kk + tig][m];
                a[i][1] = As[cur][kk + tig][m + 8];
                a[i][2] = As[cur][kk + tig + 4][m];
                a[i][3] = As[cur][kk + tig + 4][m + 8];
            }
#pragma unroll
            for (int jx = 0; jx < 8; jx++) {
                const int n = wn * 64 + jx * 8 + gid;
                b[jx][0] = Bs[cur][kk + tig][n];
                b[jx][1] = Bs[cur][kk + tig + 4][n];
            }
#pragma unroll
            for (int i = 0; i < 2; i++)
#pragma unroll
                for (int jx = 0; jx < 8; jx++)
                    mma_tf32(acc[i][jx], a[i], b[jx]);
        }
        if (pf) {
            const int nxt = cur ^ 1;
#pragma unroll
            for (int r = 0; r < 2; r++) {
                const int kk = (f0 + r) * 4;
                As[nxt][kk + 0][lm] = f2tf32(pa[r].x);
                As[nxt][kk + 1][lm] = f2tf32(pa[r].y);
                As[nxt][kk + 2][lm] = f2tf32(pa[r].z);
                As[nxt][kk + 3][lm] = f2tf32(pa[r].w);
                Bs[nxt][kk + 0][lm] = f2tf32(pb[r].x);
                Bs[nxt][kk + 1][lm] = f2tf32(pb[r].y);
                Bs[nxt][kk + 2][lm] = f2tf32(pb[r].z);
                Bs[nxt][kk + 3][lm] = f2tf32(pb[r].w);
            }
        }
        __syncthreads();
    }

#pragma unroll
    for (int i = 0; i < 2; i++) {
        const int m0 = by * 128 + wm * 32 + i * 16 + gid;
#pragma unroll
        for (int jx = 0; jx < 8; jx++) {
            const int n = bx * 128 + wn * 64 + jx * 8 + tig * 2;
            const float b0 = __ldg(bias + n);
            const float b1 = __ldg(bias + n + 1);
            float2 v0, v1;
            v0.x = acc[i][jx][0] + b0;  v0.y = acc[i][jx][1] + b1;
            v1.x = acc[i][jx][2] + b0;  v1.y = acc[i][jx][3] + b1;
            *(float2*)(C + (size_t)m0 * N + n)       = v0;
            *(float2*)(C + (size_t)(m0 + 8) * N + n) = v1;
        }
    }
}

// =============================================================================
// HMMA persistent GRU recurrence, v7 = R10 champion + LDS-optimized h operand.
//  - h operand stored [batch][k], pitch 264 (mod 32 == 8).
//  - k permuted within each 8-chunk (frag slot tig -> 2*tig, tig+4 -> 2*tig+1,
//    applied to BOTH the A-register fragments and the B loads) so each thread's
//    two b values are adjacent -> ONE LDS.64 per MMA (was 2x LDS.32, 2-way
//    conflicted). GEMM warp-LDS per CTA per step: 768 -> 384, conflict-free.
//  Everything else (geometry, mbarrier protocol, gi prefetch, gates, DSMEM
//  broadcast, numerics) identical to round 10.
// =============================================================================
#define HPITCH 264
#define OFF_HBUF(par) ((par) * (8 * HPITCH))            // 2 x 2112
#define OFF_GH        (2 * 8 * HPITCH)                  // 4224; 8x200 = 1600
#define OFF_GIS(par)  (OFF_GH + 1600 + (par) * 1536)
#define OFF_BHH       (OFF_GH + 1600 + 2 * 1536)        // 192
#define OFF_MBAR      (OFF_BHH + 192)                   // 8B aligned
#define REC_SMEM_BYTES ((OFF_MBAR + 4) * 4)             // 36,368 B

__global__ void __cluster_dims__(4, 1, 1) __launch_bounds__(384, 1)
gru_rec_mma(const float* __restrict__ Whh, const float* __restrict__ bhh_g,
            const float* __restrict__ gi, float* __restrict__ hout,
            int store_all)
{
    extern __shared__ float smf[];
    float* bhh = smf + OFF_BHH;
    float* gh  = smf + OFF_GH;
    const uint32_t mbar = (uint32_t)__cvta_generic_to_shared(smf + OFF_MBAR);

    cg::cluster_group cluster = cg::this_cluster();
    const int rank = cluster.block_rank();
    const int B0   = (blockIdx.x >> 2) * 8;       // 8 batch rows per cluster

    const int t    = threadIdx.x;
    const int lane = t & 31;
    const int w    = t >> 5;              // 0..11
    const int gid  = lane >> 2;           // 0..7
    const int tig  = lane & 3;            // 0..3

    // ---- W_hh fragments -> registers (once): warp w owns m-tile w ----
    // Permuted k within each 8-chunk: slot tig -> k=8s+2*tig, slot tig+4 -> +1.
    float wa0[32], wa1[32], wa2[32], wa3[32];
    {
        const int g  = w >> 2;
        const int r0 = g * 256 + rank * 64 + (w & 3) * 16 + gid;
        const float* p0 = Whh + (size_t)r0 * 256;
        const float* p1 = p0 + 8 * 256;
#pragma unroll
        for (int s = 0; s < 32; s++) {
            wa0[s] = f2tf32(p0[8 * s + 2 * tig]);
            wa1[s] = f2tf32(p1[8 * s + 2 * tig]);
            wa2[s] = f2tf32(p0[8 * s + 2 * tig + 1]);
            wa3[s] = f2tf32(p1[8 * s + 2 * tig + 1]);
        }
    }
    for (int i = t; i < 192; i += 384)
        bhh[i] = bhh_g[((i >> 6) << 8) + rank * 64 + (i & 63)];
    for (int i = t; i < 2 * 8 * HPITCH; i += 384) smf[i] = 0.0f;   // zero hbufs
    if (t == 0) MBAR_INIT(mbar, 4);
    __syncthreads();
    cluster.sync();                         // mbar + zeroed hbufs visible
    if (t < 4) MBAR_ARRIVE_RANK(mbar, t);   // prime phase 0: h(0) "ready"

    // gate-phase identity (threads 0..255)
    const int j     = t & 63;
    const int bb    = (t >> 6) & 3;
    const int kglob = rank * 64 + j;
    float hprev0 = 0.0f, hprev1 = 0.0f;     // exact fp32 state

    // cp.async chunk identity (384 threads x 16B = 1536 floats = 8x192)
    const int cb   = t / 48;
    const int crem = t % 48;
    const int cg_  = crem >> 4;
    const int cq   = crem & 15;
    const uint32_t gis_dst0 = (uint32_t)__cvta_generic_to_shared(
        smf + OFF_GIS(0) + cb * 192 + cg_ * 64 + cq * 4);
    const float* gi_src0 = gi + ((size_t)B0 + cb) * G3 + cg_ * 256 + rank * 64 + cq * 4;

    // prologue: gi(0) into gi_s buffer 0
    cp_async16(gis_dst0, gi_src0);
    asm volatile("cp.async.commit_group;" ::: "memory");

    for (int ts = 0; ts < T_STEPS; ts++) {
        const int par = ts & 1;

        // prefetch gi(ts+1) into the other buffer (full step of cover)
        {
            const int tn = (ts + 1 < T_STEPS) ? (ts + 1) : ts;
            cp_async16(gis_dst0 + (par ^ 1) * 1536 * 4,
                       gi_src0 + (size_t)tn * BATCH * G3);
            asm volatile("cp.async.commit_group;" ::: "memory");
        }

        MBAR_WAIT(mbar, par);                          // h(ts) visible (all CTAs)

        // ---- GEMM: D[192x8] = W @ h^T, 4 chains, LDS.64 b-fragments ----
        {
            float c0[4] = {0, 0, 0, 0}, c1[4] = {0, 0, 0, 0};
            float c2[4] = {0, 0, 0, 0}, c3[4] = {0, 0, 0, 0};
            const float* hb = smf + OFF_HBUF(par) + gid * HPITCH + 2 * tig;
#pragma unroll
            for (int s = 0; s < 32; s += 4) {
                const float2 h0 = *(const float2*)(hb + ((s + 0) << 3));
                const float2 h1 = *(const float2*)(hb + ((s + 1) << 3));
                const float2 h2 = *(const float2*)(hb + ((s + 2) << 3));
                const float2 h3 = *(const float2*)(hb + ((s + 3) << 3));
                float b0[2] = { h0.x, h0.y };
                float b1[2] = { h1.x, h1.y };
                float b2[2] = { h2.x, h2.y };
                float b3[2] = { h3.x, h3.y };
                float w0[4] = { wa0[s + 0], wa1[s + 0], wa2[s + 0], wa3[s + 0] };
                float w1[4] = { wa0[s + 1], wa1[s + 1], wa2[s + 1], wa3[s + 1] };
                float w2[4] = { wa0[s + 2], wa1[s + 2], wa2[s + 2], wa3[s + 2] };
                float w3[4] = { wa0[s + 3], wa1[s + 3], wa2[s + 3], wa3[s + 3] };
                mma_tf32(c0, w0, b0);
                mma_tf32(c1, w1, b1);
                mma_tf32(c2, w2, b2);
                mma_tf32(c3, w3, b3);
            }
            const int lr = w * 16 + gid;
            const int bi = tig * 2;
            gh[(bi    ) * 200 + lr    ] = (c0[0] + c1[0]) + (c2[0] + c3[0]);
            gh[(bi + 1) * 200 + lr    ] = (c0[1] + c1[1]) + (c2[1] + c3[1]);
            gh[(bi    ) * 200 + lr + 8] = (c0[2] + c1[2]) + (c2[2] + c3[2]);
            gh[(bi + 1) * 200 + lr + 8] = (c0[3] + c1[3]) + (c2[3] + c3[3]);
        }
        // per-thread wait for gi(ts), ALL threads, BEFORE the barrier
        asm volatile("cp.async.wait_group 1;" ::: "memory");
        __syncthreads();                               // gh + gi_s[par] ready

        // ---- gates + exact-register h update + tf32 DSMEM broadcast ----
        if (t < 256) {
            const float* gis = smf + OFF_GIS(par);
            float* hwr = smf + OFF_HBUF(par ^ 1);
            const float br = bhh[j], bz = bhh[64 + j], bn = bhh[128 + j];
#pragma unroll
            for (int i = 0; i < 2; i++) {
                const int b = bb + 4 * i;
                const float hr = gh[b * 200 + j]       + br;
                const float hz = gh[b * 200 + 64 + j]  + bz;
                const float hn = gh[b * 200 + 128 + j] + bn;
                const float ir  = gis[b * 192 + j];
                const float iz  = gis[b * 192 + 64 + j];
                const float in_ = gis[b * 192 + 128 + j];
                const float r = __fdividef(1.0f, 1.0f + __expf(-(ir + hr)));
                const float z = __fdividef(1.0f, 1.0f + __expf(-(iz + hz)));
                const float n = tanh_fast(in_ + r * hn);
                const float hprev = (i == 0) ? hprev0 : hprev1;
                const float hnew  = (1.0f - z) * n + z * hprev;
                if (i == 0) hprev0 = hnew; else hprev1 = hnew;

                const float hop = f2tf32(hnew);
                float* lp = hwr + b * HPITCH + kglob;   // [batch][k] layout
#pragma unroll
                for (int q = 0; q < 4; q++)
                    *(float*)cluster.map_shared_rank(lp, q) = hop;

                if (store_all) {
                    hout[((size_t)ts * BATCH + B0 + b) * HID + kglob] = hnew;
                } else if (ts == T_STEPS - 1) {
                    hout[(size_t)(B0 + b) * HID + kglob] = hnew;
                }
            }
        }
        __syncthreads();                     // all gates stores issued CTA-wide
        if (t < 4) MBAR_ARRIVE_RANK(mbar, t);          // signal h(ts+1) ready
    }

    // REQUIRED: no CTA may exit while peers can still DSMEM-store into its
    // SMEM (final step's gates writes).
    cluster.sync();
}

// =============================================================================
// FC on the last hidden state
// =============================================================================
__global__ __launch_bounds__(256) void fc_kernel(
    const float* __restrict__ Wfc, const float* __restrict__ bfc,
    float* __restrict__ out)
{
    __shared__ float hs[256];
    const int b = blockIdx.x;
    const int o = threadIdx.x;
    hs[o] = g_h2[b * 256 + o];
    __syncthreads();
    const float* wr = Wfc + (size_t)o * 256;
    float acc = 0.0f;
#pragma unroll 8
    for (int k = 0; k < 256; k += 4) {
        const float4 wv = *(const float4*)(wr + k);
        acc += hs[k] * wv.x + hs[k + 1] * wv.y + hs[k + 2] * wv.z + hs[k + 3] * wv.w;
    }
    out[b * 256 + o] = acc + bfc[o];
}

// =============================================================================
extern "C" void kernel_launch(void* const* d_in, const int* in_sizes, int n_in,
                              void* d_out, int out_size)
{
    const float* x     = (const float*)d_in[0];
    const float* W_ih0 = (const float*)d_in[1];
    const float* W_hh0 = (const float*)d_in[2];
    const float* b_ih0 = (const float*)d_in[3];
    const float* b_hh0 = (const float*)d_in[4];
    const float* W_ih1 = (const float*)d_in[5];
    const float* W_hh1 = (const float*)d_in[6];
    const float* b_ih1 = (const float*)d_in[7];
    const float* b_hh1 = (const float*)d_in[8];
    const float* W_fc  = (const float*)d_in[9];
    const float* b_fc  = (const float*)d_in[10];
    float* out = (float*)d_out;

    float *gi_p, *h1_p, *h2_p;
    cudaGetSymbolAddress((void**)&gi_p, g_gi);
    cudaGetSymbolAddress((void**)&h1_p, g_h1);
    cudaGetSymbolAddress((void**)&h2_p, g_h2);

    cudaFuncSetAttribute(gru_rec_mma, cudaFuncAttributeMaxDynamicSharedMemorySize,
                         REC_SMEM_BYTES);

    const int M = T_STEPS * BATCH;        // 131072
    dim3 gemm_grid(G3 / 128, M / 128);    // (6, 1024)

    // layer 0: gi0 = x @ W_ih0^T + b_ih0   (tf32 HMMA, K=128)
    gemm_tf32mma<<<gemm_grid, 256>>>(x, W_ih0, b_ih0, gi_p, G3, IN0);
    // layer 0 recurrence -> g_h1[T,B,H]   (32 clusters x 4 CTAs, 8 batch each)
    gru_rec_mma<<<128, 384, REC_SMEM_BYTES>>>(W_hh0, b_hh0, gi_p, h1_p, 1);
    // layer 1: gi1 = h1 @ W_ih1^T + b_ih1  (tf32 HMMA, K=256)
    gemm_tf32mma<<<gemm_grid, 256>>>(h1_p, W_ih1, b_ih1, gi_p, G3, HID);
    // layer 1 recurrence -> g_h2[B,H]
    gru_rec_mma<<<128, 384, REC_SMEM_BYTES>>>(W_hh1, b_hh1, gi_p, h2_p, 0);
    // FC head
    fc_kernel<<<BATCH, 256>>>(W_fc, b_fc, out);
}

// round 14
// speedup vs baseline: 2.6527x; 1.1403x over previous
#include <cuda_runtime.h>
#include <cooperative_groups.h>
#include <cstdint>

namespace cg = cooperative_groups;

#define T_STEPS 512
#define BATCH   256
#define IN0     128
#define HID     256
#define G3      768   // 3*HID

// ---------------- scratch (static device arrays; allocation-free) ------------
__device__ float g_gi[(size_t)T_STEPS * BATCH * G3];   // reused by both layers
__device__ float g_h1[(size_t)T_STEPS * BATCH * HID];  // layer-0 outputs (tf32)
__device__ float g_h2[BATCH * HID];                    // final hidden state
__device__ float g_xt[(size_t)T_STEPS * BATCH * IN0];  // x pre-rounded to tf32
__device__ float g_wt[G3 * HID];                       // W_ih* pre-rounded

// ======================= helpers ========================
__device__ __forceinline__ float f2tf32(float x) {
    float r;
    asm("cvt.rna.tf32.f32 %0, %1;" : "=f"(r) : "f"(x));
    return r;
}

__device__ __forceinline__ void mma_tf32(float* d, const float* a, const float* b) {
    asm volatile(
        "mma.sync.aligned.m16n8k8.row.col.f32.tf32.tf32.f32 "
        "{%0,%1,%2,%3}, {%4,%5,%6,%7}, {%8,%9}, {%0,%1,%2,%3};"
        : "+f"(d[0]), "+f"(d[1]), "+f"(d[2]), "+f"(d[3])
        : "r"(__float_as_uint(a[0])), "r"(__float_as_uint(a[1])),
          "r"(__float_as_uint(a[2])), "r"(__float_as_uint(a[3])),
          "r"(__float_as_uint(b[0])), "r"(__float_as_uint(b[1])));
}

__device__ __forceinline__ void cp_async16(uint32_t dst, const void* src) {
    asm volatile("cp.async.cg.shared.global [%0], [%1], 16;"
                 :: "r"(dst), "l"(src) : "memory");
}

__device__ __forceinline__ float tanh_fast(float x) {
    float r;
    asm("tanh.approx.f32 %0, %1;" : "=f"(r) : "f"(x));
    return r;
}

#define MBAR_INIT(addr, cnt) \
    asm volatile("mbarrier.init.shared.b64 [%0], %1;" \
                 :: "r"((uint32_t)(addr)), "r"((uint32_t)(cnt)) : "memory")

#define MBAR_ARRIVE_RANK(local_addr, rk)                                        \
    asm volatile("{\n\t.reg .b32 ra;\n\t"                                       \
        "mapa.shared::cluster.u32 ra, %0, %1;\n\t"                              \
        "mbarrier.arrive.release.cluster.shared::cluster.b64 _, [ra];\n\t}"     \
        :: "r"((uint32_t)(local_addr)), "r"((uint32_t)(rk)) : "memory")

#define MBAR_WAIT(addr, par) do {                                               \
    uint32_t _m = (uint32_t)(addr); uint32_t _p = (uint32_t)(par); uint32_t _d; \
    asm volatile("{\n\t.reg .pred p;\n\t"                                       \
        "mbarrier.try_wait.parity.acquire.cluster.shared::cta.b64 p, [%1], %2;\n\t" \
        "selp.b32 %0, 1, 0, p;\n\t}"                                            \
        : "=r"(_d) : "r"(_m), "r"(_p) : "memory");                              \
    if (!_d) {                                                                  \
        asm volatile("{\n\t.reg .pred P1;\n\t"                                  \
            "WL_%=:\n\t"                                                        \
            "mbarrier.try_wait.parity.acquire.cluster.shared::cta.b64 P1, [%0], %1, 0x989680;\n\t" \
            "@P1 bra.uni WD_%=;\n\t"                                            \
            "bra.uni WL_%=;\n\t"                                                \
            "WD_%=:\n\t}"                                                       \
            :: "r"(_m), "r"(_p) : "memory");                                    \
    }                                                                           \
} while (0)

// =============================================================================
// Elementwise tf32-RNA pre-rounding (vectorized): d[i] = rna(s[i])
// =============================================================================
__global__ __launch_bounds__(256) void cvt_tf32_kernel(
    const float* __restrict__ s, float* __restrict__ d, int n4)
{
    const int i = blockIdx.x * 256 + threadIdx.x;
    if (i < n4) {
        float4 v = ((const float4*)s)[i];
        v.x = f2tf32(v.x); v.y = f2tf32(v.y);
        v.z = f2tf32(v.z); v.w = f2tf32(v.w);
        ((float4*)d)[i] = v;
    }
}

// =============================================================================
// gi GEMM v2: C[M,N] = A[M,K] @ Bw[N,K]^T + bias[N], A/Bw pre-rounded tf32.
//  - cp.async 4-stage pipeline (BK=16), raw copies, no cvt in loop.
//  - smem [row][k] pitch 24 (24/2 mod 16 -> gid pattern {0,12,8,4}:
//    LDS.64 fragment loads conflict-free in both 16-lane phases).
//  - k permuted within each 8-chunk on BOTH operands (slot tig -> 2tig,
//    tig+4 -> 2tig+1): every fragment load is one LDS.64.
//  CTA 128x128, 8 warps (wm 0..3 x wn 0..1), warp tile 32x64.
// =============================================================================
#define GP    24
#define GSTG  4
#define GEMM_SMEM_BYTES (GSTG * 2 * 128 * GP * 4)   // 98,304

__global__ __launch_bounds__(256, 2) void gemm_tf32_pipe(
    const float* __restrict__ A, const float* __restrict__ Bw,
    const float* __restrict__ bias, float* __restrict__ C,
    int N, int K)
{
    extern __shared__ float gsm[];
    const uint32_t smb = (uint32_t)__cvta_generic_to_shared(gsm);

    const int t    = threadIdx.x;
    const int bx   = blockIdx.x;
    const int by   = blockIdx.y;
    const int lane = t & 31;
    const int w    = t >> 5;
    const int wm   = w & 3;
    const int wn   = w >> 2;
    const int gid  = lane >> 2;
    const int tig  = lane & 3;

    const float* Agm = A  + (size_t)(by * 128) * K;
    const float* Bgm = Bw + (size_t)(bx * 128) * K;

    // copy identity: thread moves 2 A-chunks + 2 B-chunks (16B each) per stage
    const int cm = t >> 1;            // row 0..127
    const int cq = (t & 1) * 2;       // k-quad base 0 or 2
    const uint32_t a_dst0 = smb + (cm * GP + cq * 4) * 4;
    const uint32_t b_dst0 = a_dst0 + (uint32_t)(GSTG * 128 * GP) * 4;
    const float* a_src0 = Agm + (size_t)cm * K + cq * 4;
    const float* b_src0 = Bgm + (size_t)cm * K + cq * 4;

    const int nst = K >> 4;

#define G_ISSUE(s_) do {                                                      \
    const int bf_ = (s_) & (GSTG - 1);                                        \
    const uint32_t ao_ = a_dst0 + (uint32_t)(bf_ * 128 * GP) * 4;             \
    const uint32_t bo_ = b_dst0 + (uint32_t)(bf_ * 128 * GP) * 4;             \
    const int ko_ = (s_) * 16;                                                \
    cp_async16(ao_,      a_src0 + ko_);                                       \
    cp_async16(ao_ + 16, a_src0 + ko_ + 4);                                   \
    cp_async16(bo_,      b_src0 + ko_);                                       \
    cp_async16(bo_ + 16, b_src0 + ko_ + 4);                                   \
    asm volatile("cp.async.commit_group;" ::: "memory");                      \
} while (0)

    // prologue: stages 0..2
    G_ISSUE(0);
    G_ISSUE(1);
    G_ISSUE(2);

    float acc[2][8][4];
#pragma unroll
    for (int i = 0; i < 2; i++)
#pragma unroll
        for (int jx = 0; jx < 8; jx++)
#pragma unroll
            for (int q = 0; q < 4; q++) acc[i][jx][q] = 0.0f;

    const int n0 = wn * 64;

    for (int s = 0; s < nst; s++) {
        asm volatile("cp.async.wait_group 2;" ::: "memory");
        __syncthreads();                       // stage s visible; buf(s-1) free
        if (s + GSTG - 1 < nst) G_ISSUE(s + GSTG - 1);

        const float* Asb = gsm + (s & (GSTG - 1)) * 128 * GP;
        const float* Bsb = Asb + GSTG * 128 * GP;

#pragma unroll
        for (int kk = 0; kk < 16; kk += 8) {
            const int kc = kk + 2 * tig;
            float a[2][4], b[8][2];
#pragma unroll
            for (int i = 0; i < 2; i++) {
                const int m0 = wm * 32 + i * 16;
                const float2 lo = *(const float2*)(Asb + (m0 + gid) * GP + kc);
                const float2 hi = *(const float2*)(Asb + (m0 + gid + 8) * GP + kc);
                a[i][0] = lo.x; a[i][1] = hi.x; a[i][2] = lo.y; a[i][3] = hi.y;
            }
#pragma unroll
            for (int jx = 0; jx < 8; jx++) {
                const float2 bv = *(const float2*)(Bsb + (n0 + jx * 8 + gid) * GP + kc);
                b[jx][0] = bv.x; b[jx][1] = bv.y;
            }
#pragma unroll
            for (int i = 0; i < 2; i++)
#pragma unroll
                for (int jx = 0; jx < 8; jx++)
                    mma_tf32(acc[i][jx], a[i], b[jx]);
        }
        __syncthreads();                       // all reads of stage s done
    }

    // ---- epilogue: bias + store ----
#pragma unroll
    for (int i = 0; i < 2; i++) {
        const int m0 = by * 128 + wm * 32 + i * 16 + gid;
#pragma unroll
        for (int jx = 0; jx < 8; jx++) {
            const int n = bx * 128 + wn * 64 + jx * 8 + tig * 2;
            const float b0 = __ldg(bias + n);
            const float b1 = __ldg(bias + n + 1);
            float2 v0, v1;
            v0.x = acc[i][jx][0] + b0;  v0.y = acc[i][jx][1] + b1;
            v1.x = acc[i][jx][2] + b0;  v1.y = acc[i][jx][3] + b1;
            *(float2*)(C + (size_t)m0 * N + n)       = v0;
            *(float2*)(C + (size_t)(m0 + 8) * N + n) = v1;
        }
    }
#undef G_ISSUE
}

// =============================================================================
// HMMA persistent GRU recurrence, v7 (round-13 champion, unchanged except:
// store_all path now stores hop (tf32-RNA) so gemm1 can consume pre-rounded
// h1 without a cvt -- bit-identical products to the old cvt-on-load scheme).
// =============================================================================
#define HPITCH 264
#define OFF_HBUF(par) ((par) * (8 * HPITCH))            // 2 x 2112
#define OFF_GH        (2 * 8 * HPITCH)                  // 4224; 8x200 = 1600
#define OFF_GIS(par)  (OFF_GH + 1600 + (par) * 1536)
#define OFF_BHH       (OFF_GH + 1600 + 2 * 1536)        // 192
#define OFF_MBAR      (OFF_BHH + 192)                   // 8B aligned
#define REC_SMEM_BYTES ((OFF_MBAR + 4) * 4)             // 36,368 B

__global__ void __cluster_dims__(4, 1, 1) __launch_bounds__(384, 1)
gru_rec_mma(const float* __restrict__ Whh, const float* __restrict__ bhh_g,
            const float* __restrict__ gi, float* __restrict__ hout,
            int store_all)
{
    extern __shared__ float smf[];
    float* bhh = smf + OFF_BHH;
    float* gh  = smf + OFF_GH;
    const uint32_t mbar = (uint32_t)__cvta_generic_to_shared(smf + OFF_MBAR);

    cg::cluster_group cluster = cg::this_cluster();
    const int rank = cluster.block_rank();
    const int B0   = (blockIdx.x >> 2) * 8;

    const int t    = threadIdx.x;
    const int lane = t & 31;
    const int w    = t >> 5;
    const int gid  = lane >> 2;
    const int tig  = lane & 3;

    // W_hh fragments -> registers, k permuted (slot tig -> 2tig, tig+4 -> 2tig+1)
    float wa0[32], wa1[32], wa2[32], wa3[32];
    {
        const int g  = w >> 2;
        const int r0 = g * 256 + rank * 64 + (w & 3) * 16 + gid;
        const float* p0 = Whh + (size_t)r0 * 256;
        const float* p1 = p0 + 8 * 256;
#pragma unroll
        for (int s = 0; s < 32; s++) {
            wa0[s] = f2tf32(p0[8 * s + 2 * tig]);
            wa1[s] = f2tf32(p1[8 * s + 2 * tig]);
            wa2[s] = f2tf32(p0[8 * s + 2 * tig + 1]);
            wa3[s] = f2tf32(p1[8 * s + 2 * tig + 1]);
        }
    }
    for (int i = t; i < 192; i += 384)
        bhh[i] = bhh_g[((i >> 6) << 8) + rank * 64 + (i & 63)];
    for (int i = t; i < 2 * 8 * HPITCH; i += 384) smf[i] = 0.0f;
    if (t == 0) MBAR_INIT(mbar, 4);
    __syncthreads();
    cluster.sync();
    if (t < 4) MBAR_ARRIVE_RANK(mbar, t);

    const int j     = t & 63;
    const int bb    = (t >> 6) & 3;
    const int kglob = rank * 64 + j;
    float hprev0 = 0.0f, hprev1 = 0.0f;

    const int cb   = t / 48;
    const int crem = t % 48;
    const int cg_  = crem >> 4;
    const int cq   = crem & 15;
    const uint32_t gis_dst0 = (uint32_t)__cvta_generic_to_shared(
        smf + OFF_GIS(0) + cb * 192 + cg_ * 64 + cq * 4);
    const float* gi_src0 = gi + ((size_t)B0 + cb) * G3 + cg_ * 256 + rank * 64 + cq * 4;

    cp_async16(gis_dst0, gi_src0);
    asm volatile("cp.async.commit_group;" ::: "memory");

    for (int ts = 0; ts < T_STEPS; ts++) {
        const int par = ts & 1;
        {
            const int tn = (ts + 1 < T_STEPS) ? (ts + 1) : ts;
            cp_async16(gis_dst0 + (par ^ 1) * 1536 * 4,
                       gi_src0 + (size_t)tn * BATCH * G3);
            asm volatile("cp.async.commit_group;" ::: "memory");
        }

        MBAR_WAIT(mbar, par);

        {
            float c0[4] = {0, 0, 0, 0}, c1[4] = {0, 0, 0, 0};
            float c2[4] = {0, 0, 0, 0}, c3[4] = {0, 0, 0, 0};
            const float* hb = smf + OFF_HBUF(par) + gid * HPITCH + 2 * tig;
#pragma unroll
            for (int s = 0; s < 32; s += 4) {
                const float2 h0 = *(const float2*)(hb + ((s + 0) << 3));
                const float2 h1 = *(const float2*)(hb + ((s + 1) << 3));
                const float2 h2 = *(const float2*)(hb + ((s + 2) << 3));
                const float2 h3 = *(const float2*)(hb + ((s + 3) << 3));
                float b0[2] = { h0.x, h0.y };
                float b1[2] = { h1.x, h1.y };
                float b2[2] = { h2.x, h2.y };
                float b3[2] = { h3.x, h3.y };
                float w0[4] = { wa0[s + 0], wa1[s + 0], wa2[s + 0], wa3[s + 0] };
                float w1[4] = { wa0[s + 1], wa1[s + 1], wa2[s + 1], wa3[s + 1] };
                float w2[4] = { wa0[s + 2], wa1[s + 2], wa2[s + 2], wa3[s + 2] };
                float w3[4] = { wa0[s + 3], wa1[s + 3], wa2[s + 3], wa3[s + 3] };
                mma_tf32(c0, w0, b0);
                mma_tf32(c1, w1, b1);
                mma_tf32(c2, w2, b2);
                mma_tf32(c3, w3, b3);
            }
            const int lr = w * 16 + gid;
            const int bi = tig * 2;
            gh[(bi    ) * 200 + lr    ] = (c0[0] + c1[0]) + (c2[0] + c3[0]);
            gh[(bi + 1) * 200 + lr    ] = (c0[1] + c1[1]) + (c2[1] + c3[1]);
            gh[(bi    ) * 200 + lr + 8] = (c0[2] + c1[2]) + (c2[2] + c3[2]);
            gh[(bi + 1) * 200 + lr + 8] = (c0[3] + c1[3]) + (c2[3] + c3[3]);
        }
        asm volatile("cp.async.wait_group 1;" ::: "memory");
        __syncthreads();

        if (t < 256) {
            const float* gis = smf + OFF_GIS(par);
            float* hwr = smf + OFF_HBUF(par ^ 1);
            const float br = bhh[j], bz = bhh[64 + j], bn = bhh[128 + j];
#pragma unroll
            for (int i = 0; i < 2; i++) {
                const int b = bb + 4 * i;
                const float hr = gh[b * 200 + j]       + br;
                const float hz = gh[b * 200 + 64 + j]  + bz;
                const float hn = gh[b * 200 + 128 + j] + bn;
                const float ir  = gis[b * 192 + j];
                const float iz  = gis[b * 192 + 64 + j];
                const float in_ = gis[b * 192 + 128 + j];
                const float r = __fdividef(1.0f, 1.0f + __expf(-(ir + hr)));
                const float z = __fdividef(1.0f, 1.0f + __expf(-(iz + hz)));
                const float n = tanh_fast(in_ + r * hn);
                const float hprev = (i == 0) ? hprev0 : hprev1;
                const float hnew  = (1.0f - z) * n + z * hprev;
                if (i == 0) hprev0 = hnew; else hprev1 = hnew;

                const float hop = f2tf32(hnew);
                float* lp = hwr + b * HPITCH + kglob;
#pragma unroll
                for (int q = 0; q < 4; q++)
                    *(float*)cluster.map_shared_rank(lp, q) = hop;

                if (store_all) {
                    // pre-rounded tf32 for gemm1 (same value old gemm cvt'd)
                    hout[((size_t)ts * BATCH + B0 + b) * HID + kglob] = hop;
                } else if (ts == T_STEPS - 1) {
                    hout[(size_t)(B0 + b) * HID + kglob] = hnew;  // exact for fc
                }
            }
        }
        __syncthreads();
        if (t < 4) MBAR_ARRIVE_RANK(mbar, t);
    }

    cluster.sync();
}

// =============================================================================
// FC on the last hidden state
// =============================================================================
__global__ __launch_bounds__(256) void fc_kernel(
    const float* __restrict__ Wfc, const float* __restrict__ bfc,
    float* __restrict__ out)
{
    __shared__ float hs[256];
    const int b = blockIdx.x;
    const int o = threadIdx.x;
    hs[o] = g_h2[b * 256 + o];
    __syncthreads();
    const float* wr = Wfc + (size_t)o * 256;
    float acc = 0.0f;
#pragma unroll 8
    for (int k = 0; k < 256; k += 4) {
        const float4 wv = *(const float4*)(wr + k);
        acc += hs[k] * wv.x + hs[k + 1] * wv.y + hs[k + 2] * wv.z + hs[k + 3] * wv.w;
    }
    out[b * 256 + o] = acc + bfc[o];
}

// =============================================================================
extern "C" void kernel_launch(void* const* d_in, const int* in_sizes, int n_in,
                              void* d_out, int out_size)
{
    const float* x     = (const float*)d_in[0];
    const float* W_ih0 = (const float*)d_in[1];
    const float* W_hh0 = (const float*)d_in[2];
    const float* b_ih0 = (const float*)d_in[3];
    const float* b_hh0 = (const float*)d_in[4];
    const float* W_ih1 = (const float*)d_in[5];
    const float* W_hh1 = (const float*)d_in[6];
    const float* b_ih1 = (const float*)d_in[7];
    const float* b_hh1 = (const float*)d_in[8];
    const float* W_fc  = (const float*)d_in[9];
    const float* b_fc  = (const float*)d_in[10];
    float* out = (float*)d_out;

    float *gi_p, *h1_p, *h2_p, *xt_p, *wt_p;
    cudaGetSymbolAddress((void**)&gi_p, g_gi);
    cudaGetSymbolAddress((void**)&h1_p, g_h1);
    cudaGetSymbolAddress((void**)&h2_p, g_h2);
    cudaGetSymbolAddress((void**)&xt_p, g_xt);
    cudaGetSymbolAddress((void**)&wt_p, g_wt);

    cudaFuncSetAttribute(gru_rec_mma, cudaFuncAttributeMaxDynamicSharedMemorySize,
                         REC_SMEM_BYTES);
    cudaFuncSetAttribute(gemm_tf32_pipe, cudaFuncAttributeMaxDynamicSharedMemorySize,
                         GEMM_SMEM_BYTES);

    const int M = T_STEPS * BATCH;        // 131072
    dim3 gemm_grid(G3 / 128, M / 128);    // (6, 1024)

    // pre-round x and W_ih0 to tf32 (RNA)
    {
        const int n4x = (M * IN0) / 4;                       // 4,194,304
        cvt_tf32_kernel<<<(n4x + 255) / 256, 256>>>(x, xt_p, n4x);
        const int n4w = (G3 * IN0) / 4;                      // 24,576
        cvt_tf32_kernel<<<(n4w + 255) / 256, 256>>>(W_ih0, wt_p, n4w);
    }
    // layer 0: gi0 = x @ W_ih0^T + b_ih0   (pipelined tf32 HMMA, K=128)
    gemm_tf32_pipe<<<gemm_grid, 256, GEMM_SMEM_BYTES>>>(xt_p, wt_p, b_ih0, gi_p, G3, IN0);
    // layer 0 recurrence -> g_h1[T,B,H] (stored pre-rounded tf32)
    gru_rec_mma<<<128, 384, REC_SMEM_BYTES>>>(W_hh0, b_hh0, gi_p, h1_p, 1);
    // pre-round W_ih1
    {
        const int n4w = (G3 * HID) / 4;                      // 49,152
        cvt_tf32_kernel<<<(n4w + 255) / 256, 256>>>(W_ih1, wt_p, n4w);
    }
    // layer 1: gi1 = h1 @ W_ih1^T + b_ih1  (pipelined tf32 HMMA, K=256)
    gemm_tf32_pipe<<<gemm_grid, 256, GEMM_SMEM_BYTES>>>(h1_p, wt_p, b_ih1, gi_p, G3, HID);
    // layer 1 recurrence -> g_h2[B,H]
    gru_rec_mma<<<128, 384, REC_SMEM_BYTES>>>(W_hh1, b_hh1, gi_p, h2_p, 0);
    // FC head
    fc_kernel<<<BATCH, 256>>>(W_fc, b_fc, out);
}